// round 3
// baseline (speedup 1.0000x reference)
#include <cuda_runtime.h>
#include <cuda_bf16.h>
#include <cstdint>

// Problem constants
#define BATCH   4
#define T_TXT   2048
#define T_IMG   8
#define N_LAT   64
#define DIM     2048
#define DIM_VIS 1024
#define HEADS   8
#define DIM_HEAD 64
#define INNER   (HEADS * DIM_HEAD)      // 512
#define ROWS    (BATCH * T_TXT)         // 8192
#define KVROWS  (BATCH * T_IMG * N_LAT) // 2048 total, 512 per batch
#define LN_EPS  1e-5f

// ---------------- scratch (static device, no allocs) ----------------
__device__ float g_xn[ROWS * DIM];        // 67 MB
__device__ float g_q [ROWS * INNER];      // 16.8 MB
__device__ float g_kv[KVROWS * 2 * INNER];// 8.4 MB
__device__ float g_ao[ROWS * INNER];      // 16.8 MB
__device__ int   g_qlist[BATCH][9][T_TXT];
__device__ int   g_qcount[BATCH][9];

// ---------------- LayerNorm ----------------
__global__ __launch_bounds__(256) void ln_kernel(const float* __restrict__ x,
                                                 const float* __restrict__ gamma,
                                                 const float* __restrict__ beta) {
    const int row = blockIdx.x;
    const float* xr = x + (size_t)row * DIM;
    float* out = g_xn + (size_t)row * DIM;
    const int tid = threadIdx.x;

    __shared__ float red[256];
    float s = 0.f;
    for (int c = tid; c < DIM; c += 256) s += xr[c];
    red[tid] = s; __syncthreads();
    for (int o = 128; o > 0; o >>= 1) { if (tid < o) red[tid] += red[tid + o]; __syncthreads(); }
    const float mu = red[0] * (1.0f / DIM);
    __syncthreads();

    float vs = 0.f;
    for (int c = tid; c < DIM; c += 256) { float d = xr[c] - mu; vs += d * d; }
    red[tid] = vs; __syncthreads();
    for (int o = 128; o > 0; o >>= 1) { if (tid < o) red[tid] += red[tid + o]; __syncthreads(); }
    const float rstd = rsqrtf(red[0] * (1.0f / DIM) + LN_EPS);

    for (int c = tid; c < DIM; c += 256)
        out[c] = (xr[c] - mu) * rstd * gamma[c] + beta[c];
}

// ---------------- SGEMM 128x128x8, 8x8 per thread ----------------
// C[M,N] = A[M,K] @ B[K,N], all row-major, M%128==0, N%128==0, K%8==0
__global__ __launch_bounds__(256) void sgemm128(const float* __restrict__ A,
                                                const float* __restrict__ B,
                                                float* __restrict__ C,
                                                int M, int N, int K) {
    __shared__ float As[8][128];
    __shared__ float Bs[8][128];
    const int tid = threadIdx.x;
    const int brow = blockIdx.y, bcol = blockIdx.x;
    const float* Ab = A + (size_t)brow * 128 * K;
    const float* Bb = B + (size_t)bcol * 128;

    const int tr = tid / 16, tc = tid % 16;
    const int arow = tid / 2, acol = (tid % 2) * 4;     // A: 128 rows x 8 cols
    const int browl = tid / 32, bcoll = (tid % 32) * 4; // B: 8 rows x 128 cols

    float acc[8][8];
    #pragma unroll
    for (int i = 0; i < 8; i++)
        #pragma unroll
        for (int j = 0; j < 8; j++) acc[i][j] = 0.f;

    for (int k0 = 0; k0 < K; k0 += 8) {
        float4 a = *(const float4*)(Ab + (size_t)arow * K + k0 + acol);
        As[acol + 0][arow] = a.x;
        As[acol + 1][arow] = a.y;
        As[acol + 2][arow] = a.z;
        As[acol + 3][arow] = a.w;
        float4 b = *(const float4*)(Bb + (size_t)(k0 + browl) * N + bcoll);
        *(float4*)&Bs[browl][bcoll] = b;
        __syncthreads();
        #pragma unroll
        for (int k = 0; k < 8; k++) {
            float ra[8], rb[8];
            #pragma unroll
            for (int i = 0; i < 8; i++) ra[i] = As[k][tr * 8 + i];
            #pragma unroll
            for (int j = 0; j < 8; j++) rb[j] = Bs[k][tc * 8 + j];
            #pragma unroll
            for (int i = 0; i < 8; i++)
                #pragma unroll
                for (int j = 0; j < 8; j++) acc[i][j] += ra[i] * rb[j];
        }
        __syncthreads();
    }
    #pragma unroll
    for (int i = 0; i < 8; i++) {
        float* Crow = C + (size_t)(brow * 128 + tr * 8 + i) * N + bcol * 128 + tc * 8;
        *(float4*)(Crow)     = make_float4(acc[i][0], acc[i][1], acc[i][2], acc[i][3]);
        *(float4*)(Crow + 4) = make_float4(acc[i][4], acc[i][5], acc[i][6], acc[i][7]);
    }
}

// ---------------- build per-(b,tt) query lists ----------------
// media_locations: jax bool -> harness materializes as int32 (0/1)
__global__ void build_lists(const int* __restrict__ locs) {
    const int b = threadIdx.x;
    if (b >= BATCH) return;
    int cnt[9];
    #pragma unroll
    for (int t = 0; t < 9; t++) cnt[t] = 0;
    int tt = 0;
    for (int i = 0; i < T_TXT; i++) {
        tt += (locs[b * T_TXT + i] != 0) ? 1 : 0;
        int t = tt > 8 ? 8 : tt;
        g_qlist[b][t][cnt[t]++] = i;
    }
    #pragma unroll
    for (int t = 0; t < 9; t++) g_qcount[b][t] = cnt[t];
}

// ---------------- masked chunk attention ----------------
// one block per (b, h, tt); tt==0 writes zeros. 256 threads = 8 warps,
// each warp processes one query at a time fully warp-locally.
__global__ __launch_bounds__(256) void attn_kernel() {
    const int blk = blockIdx.x;                 // b*72 + h*9 + tt
    const int b = blk / 72;
    const int h = (blk / 9) % 8;
    const int tt = blk % 9;
    const int cnt = g_qcount[b][tt];
    if (cnt == 0) return;

    const int lane = threadIdx.x & 31;
    const int warp = threadIdx.x >> 5;

    if (tt == 0) {
        for (int qi = warp; qi < cnt; qi += 8) {
            int i = g_qlist[b][0][qi];
            float* dst = g_ao + (size_t)(b * T_TXT + i) * INNER + h * DIM_HEAD;
            dst[lane] = 0.f; dst[lane + 32] = 0.f;
        }
        return;
    }

    __shared__ float ksh[64][65];
    __shared__ float vsh[64][65];
    const int base = b * 512 + (tt - 1) * 64;   // kv row base for this chunk
    for (int idx = threadIdx.x; idx < 4096; idx += 256) {
        int r = idx >> 6, c = idx & 63;
        const float* kvr = g_kv + (size_t)(base + r) * (2 * INNER);
        ksh[r][c] = kvr[h * DIM_HEAD + c];
        vsh[r][c] = kvr[INNER + h * DIM_HEAD + c];
    }
    __syncthreads();

    const float scale = 0.125f;  // dim_head^-0.5
    for (int qi = warp; qi < cnt; qi += 8) {
        const int i = g_qlist[b][tt][qi];
        const float* qr = g_q + (size_t)(b * T_TXT + i) * INNER + h * DIM_HEAD;
        const float q0 = qr[lane] * scale;
        const float q1 = qr[lane + 32] * scale;

        float s0 = 0.f, s1 = 0.f;   // scores for keys lane, lane+32
        #pragma unroll
        for (int d = 0; d < 32; d++) {
            float qd = __shfl_sync(0xffffffffu, q0, d);
            s0 += qd * ksh[lane][d];
            s1 += qd * ksh[lane + 32][d];
        }
        #pragma unroll
        for (int d = 0; d < 32; d++) {
            float qd = __shfl_sync(0xffffffffu, q1, d);
            s0 += qd * ksh[lane][d + 32];
            s1 += qd * ksh[lane + 32][d + 32];
        }
        float m = fmaxf(s0, s1);
        #pragma unroll
        for (int o = 16; o > 0; o >>= 1) m = fmaxf(m, __shfl_xor_sync(0xffffffffu, m, o));
        float p0 = __expf(s0 - m), p1 = __expf(s1 - m);
        float sum = p0 + p1;
        #pragma unroll
        for (int o = 16; o > 0; o >>= 1) sum += __shfl_xor_sync(0xffffffffu, sum, o);
        const float inv = 1.f / sum;
        p0 *= inv; p1 *= inv;

        float o0 = 0.f, o1 = 0.f;   // output dims lane, lane+32
        #pragma unroll
        for (int j = 0; j < 32; j++) {
            float pa = __shfl_sync(0xffffffffu, p0, j);
            float pb = __shfl_sync(0xffffffffu, p1, j);
            o0 += pa * vsh[j][lane]      + pb * vsh[j + 32][lane];
            o1 += pa * vsh[j][lane + 32] + pb * vsh[j + 32][lane + 32];
        }
        float* dst = g_ao + (size_t)(b * T_TXT + i) * INNER + h * DIM_HEAD;
        dst[lane] = o0; dst[lane + 32] = o1;
    }
}

// ---------------- launch ----------------
extern "C" void kernel_launch(void* const* d_in, const int* in_sizes, int n_in,
                              void* d_out, int out_size) {
    const float* x     = (const float*)d_in[0];
    const float* media = (const float*)d_in[1];
    const int*   locs  = (const int*)d_in[2];     // bool -> int32
    const float* gamma = (const float*)d_in[3];
    const float* beta  = (const float*)d_in[4];
    const float* Wq    = (const float*)d_in[5];
    const float* Wkv   = (const float*)d_in[6];
    const float* Wout  = (const float*)d_in[7];
    float*       out   = (float*)d_out;

    float *p_xn, *p_q, *p_kv, *p_ao;
    cudaGetSymbolAddress((void**)&p_xn, g_xn);
    cudaGetSymbolAddress((void**)&p_q,  g_q);
    cudaGetSymbolAddress((void**)&p_kv, g_kv);
    cudaGetSymbolAddress((void**)&p_ao, g_ao);

    // 1. LayerNorm
    ln_kernel<<<ROWS, 256>>>(x, gamma, beta);

    // 2. kv = media_flat @ Wkv   (2048 x 1024 x 1024)
    sgemm128<<<dim3((2 * INNER) / 128, KVROWS / 128), 256>>>(media, Wkv, p_kv,
                                                             KVROWS, 2 * INNER, DIM_VIS);
    // 3. q = xn @ Wq             (8192 x 512 x 2048)
    sgemm128<<<dim3(INNER / 128, ROWS / 128), 256>>>(p_xn, Wq, p_q,
                                                     ROWS, INNER, DIM);
    // 4. query grouping by text_time
    build_lists<<<1, 4>>>(locs);

    // 5. masked chunk attention
    attn_kernel<<<BATCH * HEADS * 9, 256>>>();

    // 6. out = ao @ Wout         (8192 x 2048 x 512)
    sgemm128<<<dim3(DIM / 128, ROWS / 128), 256>>>(p_ao, Wout, out,
                                                   ROWS, DIM, INNER);
}

// round 4
// speedup vs baseline: 2.1955x; 2.1955x over previous
#include <cuda_runtime.h>
#include <cuda_bf16.h>
#include <cstdint>

// Problem constants
#define BATCH   4
#define T_TXT   2048
#define T_IMG   8
#define N_LAT   64
#define DIM     2048
#define DIM_VIS 1024
#define HEADS   8
#define DIM_HEAD 64
#define INNER   (HEADS * DIM_HEAD)      // 512
#define ROWS    (BATCH * T_TXT)         // 8192
#define KVROWS  (BATCH * T_IMG * N_LAT) // 2048
#define LN_EPS  1e-5f

// ---------------- scratch (static device, no allocs) ----------------
__device__ float g_xn[ROWS * DIM];
__device__ float g_q [ROWS * INNER];
__device__ float g_kv[KVROWS * 2 * INNER];
__device__ float g_ao[ROWS * INNER];
__device__ int   g_qlist[BATCH][9][T_TXT];
__device__ int   g_qcount[BATCH][9];

// ---------------- LayerNorm (float4) ----------------
__global__ __launch_bounds__(256) void ln_kernel(const float* __restrict__ x,
                                                 const float* __restrict__ gamma,
                                                 const float* __restrict__ beta) {
    const int row = blockIdx.x;
    const float4* xr = (const float4*)(x + (size_t)row * DIM);
    float4* out = (float4*)(g_xn + (size_t)row * DIM);
    const int tid = threadIdx.x;

    __shared__ float red[256];
    float s = 0.f;
    #pragma unroll
    for (int c = tid; c < DIM / 4; c += 256) {
        float4 v = xr[c];
        s += v.x + v.y + v.z + v.w;
    }
    red[tid] = s; __syncthreads();
    for (int o = 128; o > 0; o >>= 1) { if (tid < o) red[tid] += red[tid + o]; __syncthreads(); }
    const float mu = red[0] * (1.0f / DIM);
    __syncthreads();

    float vs = 0.f;
    #pragma unroll
    for (int c = tid; c < DIM / 4; c += 256) {
        float4 v = xr[c];
        float a = v.x - mu, b = v.y - mu, cc = v.z - mu, d = v.w - mu;
        vs += a * a + b * b + cc * cc + d * d;
    }
    red[tid] = vs; __syncthreads();
    for (int o = 128; o > 0; o >>= 1) { if (tid < o) red[tid] += red[tid + o]; __syncthreads(); }
    const float rstd = rsqrtf(red[0] * (1.0f / DIM) + LN_EPS);

    const float4* g4 = (const float4*)gamma;
    const float4* b4 = (const float4*)beta;
    #pragma unroll
    for (int c = tid; c < DIM / 4; c += 256) {
        float4 v = xr[c], g = g4[c], bb = b4[c], o4;
        o4.x = (v.x - mu) * rstd * g.x + bb.x;
        o4.y = (v.y - mu) * rstd * g.y + bb.y;
        o4.z = (v.z - mu) * rstd * g.z + bb.z;
        o4.w = (v.w - mu) * rstd * g.w + bb.w;
        out[c] = o4;
    }
}

// ---------------- TF32 tensor-core GEMM ----------------
// C[M,N] = A[M,K] @ B[K,N], row-major. M%128==0, N%128==0, K%16==0.
// Block 128x128x16, 8 warps, warp tile 64x32, mma.m16n8k8.tf32.
__device__ __forceinline__ uint32_t f2tf32(float f) {
    uint32_t r;
    asm("cvt.rna.tf32.f32 %0, %1;" : "=r"(r) : "f"(f));
    return r;
}

__global__ __launch_bounds__(256) void tf32gemm(const float* __restrict__ A,
                                                const float* __restrict__ B,
                                                float* __restrict__ C,
                                                int M, int N, int K) {
    __shared__ uint32_t As[16][132];   // [k][m]
    __shared__ uint32_t Bs[16][132];   // [k][n]

    const int tid = threadIdx.x;
    const int lane = tid & 31, warp = tid >> 5;
    const int tq = lane & 3, tg = lane >> 2;
    const int wm = (warp >> 2) * 64;   // warp M offset in block (0/64)
    const int wn = (warp & 3) * 32;    // warp N offset in block (0/32/64/96)

    const float* Ab = A + (size_t)(blockIdx.y * 128) * K;
    const float* Bb = B + blockIdx.x * 128;

    const int arow = tid >> 2;          // 0..63
    const int acol = (tid & 3) * 4;     // 0,4,8,12
    const int brow = tid >> 5;          // 0..7
    const int bcol = (tid & 31) * 4;

    float acc[4][4][4];
    #pragma unroll
    for (int mf = 0; mf < 4; mf++)
        #pragma unroll
        for (int nf = 0; nf < 4; nf++)
            #pragma unroll
            for (int i = 0; i < 4; i++) acc[mf][nf][i] = 0.f;

    float4 ra0, ra1, rb0, rb1;
    ra0 = *(const float4*)(Ab + (size_t)arow * K + acol);
    ra1 = *(const float4*)(Ab + (size_t)(arow + 64) * K + acol);
    rb0 = *(const float4*)(Bb + (size_t)brow * N + bcol);
    rb1 = *(const float4*)(Bb + (size_t)(brow + 8) * N + bcol);

    for (int k0 = 0; k0 < K; k0 += 16) {
        // stage current tile into smem (tf32-rounded)
        As[acol + 0][arow] = f2tf32(ra0.x);
        As[acol + 1][arow] = f2tf32(ra0.y);
        As[acol + 2][arow] = f2tf32(ra0.z);
        As[acol + 3][arow] = f2tf32(ra0.w);
        As[acol + 0][arow + 64] = f2tf32(ra1.x);
        As[acol + 1][arow + 64] = f2tf32(ra1.y);
        As[acol + 2][arow + 64] = f2tf32(ra1.z);
        As[acol + 3][arow + 64] = f2tf32(ra1.w);
        Bs[brow][bcol + 0] = f2tf32(rb0.x);
        Bs[brow][bcol + 1] = f2tf32(rb0.y);
        Bs[brow][bcol + 2] = f2tf32(rb0.z);
        Bs[brow][bcol + 3] = f2tf32(rb0.w);
        Bs[brow + 8][bcol + 0] = f2tf32(rb1.x);
        Bs[brow + 8][bcol + 1] = f2tf32(rb1.y);
        Bs[brow + 8][bcol + 2] = f2tf32(rb1.z);
        Bs[brow + 8][bcol + 3] = f2tf32(rb1.w);
        __syncthreads();

        // prefetch next tile
        if (k0 + 16 < K) {
            ra0 = *(const float4*)(Ab + (size_t)arow * K + k0 + 16 + acol);
            ra1 = *(const float4*)(Ab + (size_t)(arow + 64) * K + k0 + 16 + acol);
            rb0 = *(const float4*)(Bb + (size_t)(k0 + 16 + brow) * N + bcol);
            rb1 = *(const float4*)(Bb + (size_t)(k0 + 16 + brow + 8) * N + bcol);
        }

        // compute 2 k-steps of 8
        #pragma unroll
        for (int ks = 0; ks < 16; ks += 8) {
            uint32_t af[4][4], bf[4][2];
            #pragma unroll
            for (int mf = 0; mf < 4; mf++) {
                af[mf][0] = As[ks + tq][wm + mf * 16 + tg];
                af[mf][1] = As[ks + tq][wm + mf * 16 + tg + 8];
                af[mf][2] = As[ks + tq + 4][wm + mf * 16 + tg];
                af[mf][3] = As[ks + tq + 4][wm + mf * 16 + tg + 8];
            }
            #pragma unroll
            for (int nf = 0; nf < 4; nf++) {
                bf[nf][0] = Bs[ks + tq][wn + nf * 8 + tg];
                bf[nf][1] = Bs[ks + tq + 4][wn + nf * 8 + tg];
            }
            #pragma unroll
            for (int mf = 0; mf < 4; mf++)
                #pragma unroll
                for (int nf = 0; nf < 4; nf++) {
                    asm volatile(
                        "mma.sync.aligned.m16n8k8.row.col.f32.tf32.tf32.f32 "
                        "{%0,%1,%2,%3}, {%4,%5,%6,%7}, {%8,%9}, {%0,%1,%2,%3};"
                        : "+f"(acc[mf][nf][0]), "+f"(acc[mf][nf][1]),
                          "+f"(acc[mf][nf][2]), "+f"(acc[mf][nf][3])
                        : "r"(af[mf][0]), "r"(af[mf][1]), "r"(af[mf][2]), "r"(af[mf][3]),
                          "r"(bf[nf][0]), "r"(bf[nf][1]));
                }
        }
        __syncthreads();
    }

    // epilogue
    #pragma unroll
    for (int mf = 0; mf < 4; mf++) {
        const int row0 = blockIdx.y * 128 + wm + mf * 16 + tg;
        #pragma unroll
        for (int nf = 0; nf < 4; nf++) {
            const int col = blockIdx.x * 128 + wn + nf * 8 + 2 * tq;
            *(float2*)(C + (size_t)row0 * N + col) =
                make_float2(acc[mf][nf][0], acc[mf][nf][1]);
            *(float2*)(C + (size_t)(row0 + 8) * N + col) =
                make_float2(acc[mf][nf][2], acc[mf][nf][3]);
        }
    }
}

// ---------------- parallel build of per-(b,tt) query lists ----------------
// one block per batch row; block-wide inclusive scan of media_locations,
// then shared-atomic append (order within a list is irrelevant).
__global__ __launch_bounds__(256) void build_lists2(const int* __restrict__ locs) {
    const int b = blockIdx.x;
    const int tid = threadIdx.x;
    __shared__ int ssum[256];
    __shared__ int cnt[9];

    const int base = tid * 8;           // 256*8 = 2048
    int v[8];
    int s = 0;
    #pragma unroll
    for (int j = 0; j < 8; j++) { v[j] = locs[b * T_TXT + base + j]; s += v[j]; }
    ssum[tid] = s;
    if (tid < 9) cnt[tid] = 0;
    __syncthreads();
    // Hillis-Steele inclusive scan over per-thread sums
    for (int off = 1; off < 256; off <<= 1) {
        int t = (tid >= off) ? ssum[tid - off] : 0;
        __syncthreads();
        ssum[tid] += t;
        __syncthreads();
    }
    int run = ssum[tid] - s;            // exclusive prefix
    #pragma unroll
    for (int j = 0; j < 8; j++) {
        run += v[j];                    // inclusive text_time, 0..8
        int p = atomicAdd(&cnt[run], 1);
        g_qlist[b][run][p] = base + j;
    }
    __syncthreads();
    if (tid < 9) g_qcount[b][tid] = cnt[tid];
}

// ---------------- masked chunk attention ----------------
__global__ __launch_bounds__(256) void attn_kernel() {
    const int blk = blockIdx.x;                 // b*72 + h*9 + tt
    const int b = blk / 72;
    const int h = (blk / 9) % 8;
    const int tt = blk % 9;
    const int cnt = g_qcount[b][tt];
    if (cnt == 0) return;

    const int lane = threadIdx.x & 31;
    const int warp = threadIdx.x >> 5;

    if (tt == 0) {
        for (int qi = warp; qi < cnt; qi += 8) {
            int i = g_qlist[b][0][qi];
            float* dst = g_ao + (size_t)(b * T_TXT + i) * INNER + h * DIM_HEAD;
            dst[lane] = 0.f; dst[lane + 32] = 0.f;
        }
        return;
    }

    __shared__ float ksh[64][65];
    __shared__ float vsh[64][65];
    const int base = b * 512 + (tt - 1) * 64;
    for (int idx = threadIdx.x; idx < 4096; idx += 256) {
        int r = idx >> 6, c = idx & 63;
        const float* kvr = g_kv + (size_t)(base + r) * (2 * INNER);
        ksh[r][c] = kvr[h * DIM_HEAD + c];
        vsh[r][c] = kvr[INNER + h * DIM_HEAD + c];
    }
    __syncthreads();

    const float scale = 0.125f;
    for (int qi = warp; qi < cnt; qi += 8) {
        const int i = g_qlist[b][tt][qi];
        const float* qr = g_q + (size_t)(b * T_TXT + i) * INNER + h * DIM_HEAD;
        const float q0 = qr[lane] * scale;
        const float q1 = qr[lane + 32] * scale;

        float s0 = 0.f, s1 = 0.f;
        #pragma unroll
        for (int d = 0; d < 32; d++) {
            float qd = __shfl_sync(0xffffffffu, q0, d);
            s0 += qd * ksh[lane][d];
            s1 += qd * ksh[lane + 32][d];
        }
        #pragma unroll
        for (int d = 0; d < 32; d++) {
            float qd = __shfl_sync(0xffffffffu, q1, d);
            s0 += qd * ksh[lane][d + 32];
            s1 += qd * ksh[lane + 32][d + 32];
        }
        float m = fmaxf(s0, s1);
        #pragma unroll
        for (int o = 16; o > 0; o >>= 1) m = fmaxf(m, __shfl_xor_sync(0xffffffffu, m, o));
        float p0 = __expf(s0 - m), p1 = __expf(s1 - m);
        float sum = p0 + p1;
        #pragma unroll
        for (int o = 16; o > 0; o >>= 1) sum += __shfl_xor_sync(0xffffffffu, sum, o);
        const float inv = 1.f / sum;
        p0 *= inv; p1 *= inv;

        float o0 = 0.f, o1 = 0.f;
        #pragma unroll
        for (int j = 0; j < 32; j++) {
            float pa = __shfl_sync(0xffffffffu, p0, j);
            float pb = __shfl_sync(0xffffffffu, p1, j);
            o0 += pa * vsh[j][lane]      + pb * vsh[j + 32][lane];
            o1 += pa * vsh[j][lane + 32] + pb * vsh[j + 32][lane + 32];
        }
        float* dst = g_ao + (size_t)(b * T_TXT + i) * INNER + h * DIM_HEAD;
        dst[lane] = o0; dst[lane + 32] = o1;
    }
}

// ---------------- launch ----------------
extern "C" void kernel_launch(void* const* d_in, const int* in_sizes, int n_in,
                              void* d_out, int out_size) {
    const float* x     = (const float*)d_in[0];
    const float* media = (const float*)d_in[1];
    const int*   locs  = (const int*)d_in[2];
    const float* gamma = (const float*)d_in[3];
    const float* beta  = (const float*)d_in[4];
    const float* Wq    = (const float*)d_in[5];
    const float* Wkv   = (const float*)d_in[6];
    const float* Wout  = (const float*)d_in[7];
    float*       out   = (float*)d_out;

    float *p_xn, *p_q, *p_kv, *p_ao;
    cudaGetSymbolAddress((void**)&p_xn, g_xn);
    cudaGetSymbolAddress((void**)&p_q,  g_q);
    cudaGetSymbolAddress((void**)&p_kv, g_kv);
    cudaGetSymbolAddress((void**)&p_ao, g_ao);

    // 1. LayerNorm
    ln_kernel<<<ROWS, 256>>>(x, gamma, beta);

    // 2. kv = media_flat @ Wkv   (2048 x 1024 x 1024)
    tf32gemm<<<dim3((2 * INNER) / 128, KVROWS / 128), 256>>>(media, Wkv, p_kv,
                                                             KVROWS, 2 * INNER, DIM_VIS);
    // 3. q = xn @ Wq             (8192 x 512 x 2048)
    tf32gemm<<<dim3(INNER / 128, ROWS / 128), 256>>>(p_xn, Wq, p_q,
                                                     ROWS, INNER, DIM);
    // 4. query grouping by text_time (parallel scan)
    build_lists2<<<BATCH, 256>>>(locs);

    // 5. masked chunk attention
    attn_kernel<<<BATCH * HEADS * 9, 256>>>();

    // 6. out = ao @ Wout         (8192 x 2048 x 512)
    tf32gemm<<<dim3(DIM / 128, ROWS / 128), 256>>>(p_ao, Wout, out,
                                                   ROWS, DIM, INNER);
}

// round 5
// speedup vs baseline: 2.5011x; 1.1392x over previous
#include <cuda_runtime.h>
#include <cuda_bf16.h>
#include <cstdint>

// Problem constants
#define BATCH   4
#define T_TXT   2048
#define T_IMG   8
#define N_LAT   64
#define DIM     2048
#define DIM_VIS 1024
#define HEADS   8
#define DIM_HEAD 64
#define INNER   (HEADS * DIM_HEAD)      // 512
#define ROWS    (BATCH * T_TXT)         // 8192
#define KVROWS  (BATCH * T_IMG * N_LAT) // 2048
#define LN_EPS  1e-5f

// ---------------- scratch (static device, no allocs) ----------------
__device__ float g_xn[ROWS * DIM];
__device__ float g_q [ROWS * INNER];
__device__ float g_kv[KVROWS * 2 * INNER];
__device__ float g_ao[ROWS * INNER];
__device__ int   g_qlist[BATCH][9][T_TXT];
__device__ int   g_qcount[BATCH][9];

// ---------------- LayerNorm (single pass, float4) ----------------
__global__ __launch_bounds__(256) void ln_kernel(const float* __restrict__ x,
                                                 const float* __restrict__ gamma,
                                                 const float* __restrict__ beta) {
    const int row = blockIdx.x;
    const float4* xr = (const float4*)(x + (size_t)row * DIM);
    float4* out = (float4*)(g_xn + (size_t)row * DIM);
    const int tid = threadIdx.x;

    __shared__ float reds[256], redq[256];
    float s = 0.f, sq = 0.f;
    #pragma unroll
    for (int c = tid; c < DIM / 4; c += 256) {
        float4 v = xr[c];
        s  += v.x + v.y + v.z + v.w;
        sq += v.x * v.x + v.y * v.y + v.z * v.z + v.w * v.w;
    }
    reds[tid] = s; redq[tid] = sq; __syncthreads();
    for (int o = 128; o > 0; o >>= 1) {
        if (tid < o) { reds[tid] += reds[tid + o]; redq[tid] += redq[tid + o]; }
        __syncthreads();
    }
    const float mu = reds[0] * (1.0f / DIM);
    const float var = redq[0] * (1.0f / DIM) - mu * mu;
    const float rstd = rsqrtf(var + LN_EPS);

    const float4* g4 = (const float4*)gamma;
    const float4* b4 = (const float4*)beta;
    #pragma unroll
    for (int c = tid; c < DIM / 4; c += 256) {
        float4 v = xr[c], g = g4[c], bb = b4[c], o4;
        o4.x = (v.x - mu) * rstd * g.x + bb.x;
        o4.y = (v.y - mu) * rstd * g.y + bb.y;
        o4.z = (v.z - mu) * rstd * g.z + bb.z;
        o4.w = (v.w - mu) * rstd * g.w + bb.w;
        out[c] = o4;
    }
}

// ---------------- TF32 tensor-core GEMM (double-buffered) ----------------
// C[M,N] = A[M,K] @ B[K,N], row-major. M%128==0, N%128==0, K%16==0.
// Block 128x128x16, 8 warps, warp tile 64x32, mma.m16n8k8.tf32.
// A smem: [m][k] pad 20 (conflict-free frag loads + STS.128 stores)
// B smem: [k][n] pad 136 (conflict-free frag loads + STS.128 stores)
#define PA 20
#define PB 136

__device__ __forceinline__ uint32_t f2tf32(float f) {
    uint32_t r;
    asm("cvt.rna.tf32.f32 %0, %1;" : "=r"(r) : "f"(f));
    return r;
}
__device__ __forceinline__ uint4 cvt4(float4 v) {
    uint4 u;
    u.x = f2tf32(v.x); u.y = f2tf32(v.y); u.z = f2tf32(v.z); u.w = f2tf32(v.w);
    return u;
}

__global__ __launch_bounds__(256) void tf32gemm(const float* __restrict__ A,
                                                const float* __restrict__ B,
                                                float* __restrict__ C,
                                                int M, int N, int K) {
    __shared__ uint32_t As[2][128][PA];
    __shared__ uint32_t Bs[2][16][PB];

    const int tid = threadIdx.x;
    const int lane = tid & 31, warp = tid >> 5;
    const int tq = lane & 3, tg = lane >> 2;
    const int wm = (warp >> 2) * 64;   // 0/64
    const int wn = (warp & 3) * 32;    // 0/32/64/96

    const float* Ab = A + (size_t)(blockIdx.y * 128) * K;
    const float* Bb = B + blockIdx.x * 128;

    const int arow = tid >> 2;          // 0..63 (and +64)
    const int acol = (tid & 3) * 4;     // 0,4,8,12
    const int brow = tid >> 5;          // 0..7 (and +8)
    const int bcol = (tid & 31) * 4;

    float acc[4][4][4];
    #pragma unroll
    for (int mf = 0; mf < 4; mf++)
        #pragma unroll
        for (int nf = 0; nf < 4; nf++)
            #pragma unroll
            for (int i = 0; i < 4; i++) acc[mf][nf][i] = 0.f;

    float4 ra0, ra1, rb0, rb1;
    ra0 = *(const float4*)(Ab + (size_t)arow * K + acol);
    ra1 = *(const float4*)(Ab + (size_t)(arow + 64) * K + acol);
    rb0 = *(const float4*)(Bb + (size_t)brow * N + bcol);
    rb1 = *(const float4*)(Bb + (size_t)(brow + 8) * N + bcol);

    // stage 0
    *(uint4*)&As[0][arow][acol]      = cvt4(ra0);
    *(uint4*)&As[0][arow + 64][acol] = cvt4(ra1);
    *(uint4*)&Bs[0][brow][bcol]      = cvt4(rb0);
    *(uint4*)&Bs[0][brow + 8][bcol]  = cvt4(rb1);
    __syncthreads();

    int buf = 0;
    for (int k0 = 0; k0 < K; k0 += 16, buf ^= 1) {
        const bool more = (k0 + 16) < K;
        if (more) {
            ra0 = *(const float4*)(Ab + (size_t)arow * K + k0 + 16 + acol);
            ra1 = *(const float4*)(Ab + (size_t)(arow + 64) * K + k0 + 16 + acol);
            rb0 = *(const float4*)(Bb + (size_t)(k0 + 16 + brow) * N + bcol);
            rb1 = *(const float4*)(Bb + (size_t)(k0 + 16 + brow + 8) * N + bcol);
        }

        #pragma unroll
        for (int ks = 0; ks < 16; ks += 8) {
            uint32_t af[4][4], bf[4][2];
            #pragma unroll
            for (int mf = 0; mf < 4; mf++) {
                af[mf][0] = As[buf][wm + mf * 16 + tg][ks + tq];
                af[mf][1] = As[buf][wm + mf * 16 + tg + 8][ks + tq];
                af[mf][2] = As[buf][wm + mf * 16 + tg][ks + tq + 4];
                af[mf][3] = As[buf][wm + mf * 16 + tg + 8][ks + tq + 4];
            }
            #pragma unroll
            for (int nf = 0; nf < 4; nf++) {
                bf[nf][0] = Bs[buf][ks + tq][wn + nf * 8 + tg];
                bf[nf][1] = Bs[buf][ks + tq + 4][wn + nf * 8 + tg];
            }
            #pragma unroll
            for (int mf = 0; mf < 4; mf++)
                #pragma unroll
                for (int nf = 0; nf < 4; nf++) {
                    asm volatile(
                        "mma.sync.aligned.m16n8k8.row.col.f32.tf32.tf32.f32 "
                        "{%0,%1,%2,%3}, {%4,%5,%6,%7}, {%8,%9}, {%0,%1,%2,%3};"
                        : "+f"(acc[mf][nf][0]), "+f"(acc[mf][nf][1]),
                          "+f"(acc[mf][nf][2]), "+f"(acc[mf][nf][3])
                        : "r"(af[mf][0]), "r"(af[mf][1]), "r"(af[mf][2]), "r"(af[mf][3]),
                          "r"(bf[nf][0]), "r"(bf[nf][1]));
                }
        }

        if (more) {
            *(uint4*)&As[buf ^ 1][arow][acol]      = cvt4(ra0);
            *(uint4*)&As[buf ^ 1][arow + 64][acol] = cvt4(ra1);
            *(uint4*)&Bs[buf ^ 1][brow][bcol]      = cvt4(rb0);
            *(uint4*)&Bs[buf ^ 1][brow + 8][bcol]  = cvt4(rb1);
        }
        __syncthreads();
    }

    // epilogue
    #pragma unroll
    for (int mf = 0; mf < 4; mf++) {
        const int row0 = blockIdx.y * 128 + wm + mf * 16 + tg;
        #pragma unroll
        for (int nf = 0; nf < 4; nf++) {
            const int col = blockIdx.x * 128 + wn + nf * 8 + 2 * tq;
            *(float2*)(C + (size_t)row0 * N + col) =
                make_float2(acc[mf][nf][0], acc[mf][nf][1]);
            *(float2*)(C + (size_t)(row0 + 8) * N + col) =
                make_float2(acc[mf][nf][2], acc[mf][nf][3]);
        }
    }
}

// ---------------- parallel build of per-(b,tt) query lists ----------------
__global__ __launch_bounds__(256) void build_lists2(const int* __restrict__ locs) {
    const int b = blockIdx.x;
    const int tid = threadIdx.x;
    __shared__ int ssum[256];
    __shared__ int cnt[9];

    const int base = tid * 8;           // 256*8 = 2048
    int v[8];
    int s = 0;
    #pragma unroll
    for (int j = 0; j < 8; j++) { v[j] = locs[b * T_TXT + base + j]; s += v[j]; }
    ssum[tid] = s;
    if (tid < 9) cnt[tid] = 0;
    __syncthreads();
    for (int off = 1; off < 256; off <<= 1) {
        int t = (tid >= off) ? ssum[tid - off] : 0;
        __syncthreads();
        ssum[tid] += t;
        __syncthreads();
    }
    int run = ssum[tid] - s;            // exclusive prefix
    #pragma unroll
    for (int j = 0; j < 8; j++) {
        run += v[j];                    // inclusive text_time, 0..8
        int p = atomicAdd(&cnt[run], 1);
        g_qlist[b][run][p] = base + j;
    }
    __syncthreads();
    if (tid < 9) g_qcount[b][tid] = cnt[tid];
}

// ---------------- masked chunk attention ----------------
__global__ __launch_bounds__(256) void attn_kernel() {
    const int blk = blockIdx.x;                 // b*72 + h*9 + tt
    const int b = blk / 72;
    const int h = (blk / 9) % 8;
    const int tt = blk % 9;
    const int cnt = g_qcount[b][tt];
    if (cnt == 0) return;

    const int lane = threadIdx.x & 31;
    const int warp = threadIdx.x >> 5;

    if (tt == 0) {
        for (int qi = warp; qi < cnt; qi += 8) {
            int i = g_qlist[b][0][qi];
            float* dst = g_ao + (size_t)(b * T_TXT + i) * INNER + h * DIM_HEAD;
            dst[lane] = 0.f; dst[lane + 32] = 0.f;
        }
        return;
    }

    __shared__ float ksh[64][65];
    __shared__ float vsh[64][65];
    const int base = b * 512 + (tt - 1) * 64;
    for (int idx = threadIdx.x; idx < 4096; idx += 256) {
        int r = idx >> 6, c = idx & 63;
        const float* kvr = g_kv + (size_t)(base + r) * (2 * INNER);
        ksh[r][c] = kvr[h * DIM_HEAD + c];
        vsh[r][c] = kvr[INNER + h * DIM_HEAD + c];
    }
    __syncthreads();

    const float scale = 0.125f;
    for (int qi = warp; qi < cnt; qi += 8) {
        const int i = g_qlist[b][tt][qi];
        const float* qr = g_q + (size_t)(b * T_TXT + i) * INNER + h * DIM_HEAD;
        const float q0 = qr[lane] * scale;
        const float q1 = qr[lane + 32] * scale;

        float s0 = 0.f, s1 = 0.f;
        #pragma unroll
        for (int d = 0; d < 32; d++) {
            float qd = __shfl_sync(0xffffffffu, q0, d);
            s0 += qd * ksh[lane][d];
            s1 += qd * ksh[lane + 32][d];
        }
        #pragma unroll
        for (int d = 0; d < 32; d++) {
            float qd = __shfl_sync(0xffffffffu, q1, d);
            s0 += qd * ksh[lane][d + 32];
            s1 += qd * ksh[lane + 32][d + 32];
        }
        float m = fmaxf(s0, s1);
        #pragma unroll
        for (int o = 16; o > 0; o >>= 1) m = fmaxf(m, __shfl_xor_sync(0xffffffffu, m, o));
        float p0 = __expf(s0 - m), p1 = __expf(s1 - m);
        float sum = p0 + p1;
        #pragma unroll
        for (int o = 16; o > 0; o >>= 1) sum += __shfl_xor_sync(0xffffffffu, sum, o);
        const float inv = 1.f / sum;
        p0 *= inv; p1 *= inv;

        float o0 = 0.f, o1 = 0.f;
        #pragma unroll
        for (int j = 0; j < 32; j++) {
            float pa = __shfl_sync(0xffffffffu, p0, j);
            float pb = __shfl_sync(0xffffffffu, p1, j);
            o0 += pa * vsh[j][lane]      + pb * vsh[j + 32][lane];
            o1 += pa * vsh[j][lane + 32] + pb * vsh[j + 32][lane + 32];
        }
        float* dst = g_ao + (size_t)(b * T_TXT + i) * INNER + h * DIM_HEAD;
        dst[lane] = o0; dst[lane + 32] = o1;
    }
}

// ---------------- launch ----------------
extern "C" void kernel_launch(void* const* d_in, const int* in_sizes, int n_in,
                              void* d_out, int out_size) {
    const float* x     = (const float*)d_in[0];
    const float* media = (const float*)d_in[1];
    const int*   locs  = (const int*)d_in[2];
    const float* gamma = (const float*)d_in[3];
    const float* beta  = (const float*)d_in[4];
    const float* Wq    = (const float*)d_in[5];
    const float* Wkv   = (const float*)d_in[6];
    const float* Wout  = (const float*)d_in[7];
    float*       out   = (float*)d_out;

    float *p_xn, *p_q, *p_kv, *p_ao;
    cudaGetSymbolAddress((void**)&p_xn, g_xn);
    cudaGetSymbolAddress((void**)&p_q,  g_q);
    cudaGetSymbolAddress((void**)&p_kv, g_kv);
    cudaGetSymbolAddress((void**)&p_ao, g_ao);

    // 1. LayerNorm
    ln_kernel<<<ROWS, 256>>>(x, gamma, beta);

    // 2. kv = media_flat @ Wkv   (2048 x 1024 x 1024)
    tf32gemm<<<dim3((2 * INNER) / 128, KVROWS / 128), 256>>>(media, Wkv, p_kv,
                                                             KVROWS, 2 * INNER, DIM_VIS);
    // 3. q = xn @ Wq             (8192 x 512 x 2048)
    tf32gemm<<<dim3(INNER / 128, ROWS / 128), 256>>>(p_xn, Wq, p_q,
                                                     ROWS, INNER, DIM);
    // 4. query grouping by text_time (parallel scan)
    build_lists2<<<BATCH, 256>>>(locs);

    // 5. masked chunk attention
    attn_kernel<<<BATCH * HEADS * 9, 256>>>();

    // 6. out = ao @ Wout         (8192 x 2048 x 512)
    tf32gemm<<<dim3(DIM / 128, ROWS / 128), 256>>>(p_ao, Wout, out,
                                                   ROWS, DIM, INNER);
}

// round 7
// speedup vs baseline: 2.8013x; 1.1200x over previous
#include <cuda_runtime.h>
#include <cuda_bf16.h>
#include <cstdint>

// Problem constants
#define BATCH   4
#define T_TXT   2048
#define T_IMG   8
#define N_LAT   64
#define DIM     2048
#define DIM_VIS 1024
#define HEADS   8
#define DIM_HEAD 64
#define INNER   (HEADS * DIM_HEAD)      // 512
#define ROWS    (BATCH * T_TXT)         // 8192
#define KVROWS  (BATCH * T_IMG * N_LAT) // 2048
#define LN_EPS  1e-5f

// ---------------- scratch (static device, no allocs) ----------------
__device__ float g_xn[ROWS * DIM];
__device__ float g_q [ROWS * INNER];
__device__ float g_kv[KVROWS * 2 * INNER];
__device__ float g_ao[ROWS * INNER];
__device__ float g_wq_t [DIM * INNER];
__device__ float g_wkv_t[DIM_VIS * 2 * INNER];
__device__ float g_wout_t[INNER * DIM];
__device__ float g_media_t[KVROWS * DIM_VIS];
__device__ int   g_qlist[BATCH][9][T_TXT];
__device__ int   g_qcount[BATCH][9];

__device__ __forceinline__ uint32_t f2tf32(float f) {
    uint32_t r;
    asm("cvt.rna.tf32.f32 %0, %1;" : "=r"(r) : "f"(f));
    return r;
}
__device__ __forceinline__ float rnd_tf32(float f) { return __uint_as_float(f2tf32(f)); }
__device__ __forceinline__ uint32_t smem_u32(const void* p) {
    uint32_t a;
    asm("{ .reg .u64 t; cvta.to.shared.u64 t, %1; cvt.u32.u64 %0, t; }" : "=r"(a) : "l"(p));
    return a;
}

#define CP_ASYNC16(dst, src) \
    asm volatile("cp.async.cg.shared.global [%0], [%1], 16;" :: "r"(dst), "l"(src))
#define CP_COMMIT() asm volatile("cp.async.commit_group;" ::: "memory")
#define CP_WAIT1()  asm volatile("cp.async.wait_group 1;" ::: "memory")

// ---------------- cp.async 3-stage pipelined TF32 GEMM ----------------
// C[M,N] = A[M,K] @ B[K,N], row-major fp32 PRE-ROUNDED to tf32 (rna).
// Block 128x128, KT=32, 256 threads (8 warps), warp tile 64x32, 3 stages.
#define KT 32
#define PA 36                 // floats per A smem row (128 rows)
#define PB 136                // floats per B smem row (32 rows)
#define A_STG_BYTES (128 * PA * 4)   // 18432
#define B_STG_BYTES (KT * PB * 4)    // 17408
#define STAGES 3
#define SMEM_BYTES (STAGES * (A_STG_BYTES + B_STG_BYTES))  // 107520

__global__ __launch_bounds__(256) void tf32gemm_pipe(const float* __restrict__ A,
                                                     const float* __restrict__ B,
                                                     float* __restrict__ C,
                                                     int M, int N, int K) {
    extern __shared__ char smem[];
    const uint32_t sb = smem_u32(smem);
    const int tid = threadIdx.x;
    const int lane = tid & 31, warp = tid >> 5;
    const int tq = lane & 3, tg = lane >> 2;
    const int wm = (warp >> 2) * 64;   // 0/64
    const int wn = (warp & 3) * 32;    // 0/32/64/96

    const int mblk = blockIdx.y * 128;
    const int nblk = blockIdx.x * 128;
    const float* Ab = A + (size_t)mblk * K;
    const float* Bb = B + nblk;

    // load mapping: 1024 16B-chunks per stage for each of A and B.
    const int a_row = tid >> 1;                 // with i*128: rows 0..127, 8 chunks/row
    const int b_row = tid >> 5;                 // with i*8:  rows 0..31, 32 chunks/row

    float acc[4][4][4];
    #pragma unroll
    for (int mf = 0; mf < 4; mf++)
        #pragma unroll
        for (int nf = 0; nf < 4; nf++)
            #pragma unroll
            for (int i = 0; i < 4; i++) acc[mf][nf][i] = 0.f;

    const int nK = K / KT;

    // issue loads for stage s covering K range [c*KT, c*KT+KT)
    auto issue = [&](int s, int c) {
        const uint32_t sa = sb + s * (A_STG_BYTES + B_STG_BYTES);
        const uint32_t sB = sa + A_STG_BYTES;
        const int k0 = c * KT;
        #pragma unroll
        for (int i = 0; i < 4; i++) {           // A: 4 chunks/thread
            int id = tid + i * 256;             // 0..1023
            int row = id >> 3, c4 = id & 7;
            CP_ASYNC16(sa + row * (PA * 4) + c4 * 16,
                       Ab + (size_t)row * K + k0 + c4 * 4);
        }
        #pragma unroll
        for (int i = 0; i < 4; i++) {           // B: 4 chunks/thread
            int id = tid + i * 256;
            int row = id >> 5, c4 = id & 31;
            CP_ASYNC16(sB + row * (PB * 4) + c4 * 16,
                       Bb + (size_t)(k0 + row) * N + c4 * 4);
        }
    };

    issue(0, 0); CP_COMMIT();
    if (nK > 1) issue(1, 1);
    CP_COMMIT();

    int buf = 0;
    for (int c = 0; c < nK; c++) {
        CP_WAIT1();
        __syncthreads();
        // prefetch stage c+2 into buffer (c+2)%3 (freed after iter c-1)
        if (c + 2 < nK) issue((c + 2) % STAGES, c + 2);
        CP_COMMIT();

        const float* As = (const float*)(smem + buf * (A_STG_BYTES + B_STG_BYTES));
        const float* Bs = (const float*)(smem + buf * (A_STG_BYTES + B_STG_BYTES) + A_STG_BYTES);

        #pragma unroll
        for (int ks = 0; ks < KT; ks += 8) {
            uint32_t af[4][4], bf[4][2];
            #pragma unroll
            for (int mf = 0; mf < 4; mf++) {
                const int m0 = wm + mf * 16 + tg;
                af[mf][0] = __float_as_uint(As[m0 * PA + ks + tq]);
                af[mf][1] = __float_as_uint(As[(m0 + 8) * PA + ks + tq]);
                af[mf][2] = __float_as_uint(As[m0 * PA + ks + tq + 4]);
                af[mf][3] = __float_as_uint(As[(m0 + 8) * PA + ks + tq + 4]);
            }
            #pragma unroll
            for (int nf = 0; nf < 4; nf++) {
                bf[nf][0] = __float_as_uint(Bs[(ks + tq) * PB + wn + nf * 8 + tg]);
                bf[nf][1] = __float_as_uint(Bs[(ks + tq + 4) * PB + wn + nf * 8 + tg]);
            }
            #pragma unroll
            for (int mf = 0; mf < 4; mf++)
                #pragma unroll
                for (int nf = 0; nf < 4; nf++) {
                    asm volatile(
                        "mma.sync.aligned.m16n8k8.row.col.f32.tf32.tf32.f32 "
                        "{%0,%1,%2,%3}, {%4,%5,%6,%7}, {%8,%9}, {%0,%1,%2,%3};"
                        : "+f"(acc[mf][nf][0]), "+f"(acc[mf][nf][1]),
                          "+f"(acc[mf][nf][2]), "+f"(acc[mf][nf][3])
                        : "r"(af[mf][0]), "r"(af[mf][1]), "r"(af[mf][2]), "r"(af[mf][3]),
                          "r"(bf[nf][0]), "r"(bf[nf][1]));
                }
        }
        __syncthreads();
        buf = (buf + 1) % STAGES;
    }

    // epilogue
    #pragma unroll
    for (int mf = 0; mf < 4; mf++) {
        const int row0 = mblk + wm + mf * 16 + tg;
        #pragma unroll
        for (int nf = 0; nf < 4; nf++) {
            const int col = nblk + wn + nf * 8 + 2 * tq;
            *(float2*)(C + (size_t)row0 * N + col) =
                make_float2(acc[mf][nf][0], acc[mf][nf][1]);
            *(float2*)(C + (size_t)(row0 + 8) * N + col) =
                make_float2(acc[mf][nf][2], acc[mf][nf][3]);
        }
    }
}

// ---------------- tf32 pre-round (rna) for weights/media ----------------
__global__ __launch_bounds__(256) void cvt_tf32_kernel(const float* __restrict__ in,
                                                       float* __restrict__ out, int n4) {
    int i = blockIdx.x * 256 + threadIdx.x;
    if (i < n4) {
        float4 v = ((const float4*)in)[i];
        v.x = rnd_tf32(v.x); v.y = rnd_tf32(v.y); v.z = rnd_tf32(v.z); v.w = rnd_tf32(v.w);
        ((float4*)out)[i] = v;
    }
}

// ---------------- LayerNorm (single pass, tf32-rounded output) ----------------
__global__ __launch_bounds__(256) void ln_kernel(const float* __restrict__ x,
                                                 const float* __restrict__ gamma,
                                                 const float* __restrict__ beta) {
    const int row = blockIdx.x;
    const float4* xr = (const float4*)(x + (size_t)row * DIM);
    float4* out = (float4*)(g_xn + (size_t)row * DIM);
    const int tid = threadIdx.x;

    __shared__ float reds[256], redq[256];
    float s = 0.f, sq = 0.f;
    #pragma unroll
    for (int c = tid; c < DIM / 4; c += 256) {
        float4 v = xr[c];
        s  += v.x + v.y + v.z + v.w;
        sq += v.x * v.x + v.y * v.y + v.z * v.z + v.w * v.w;
    }
    reds[tid] = s; redq[tid] = sq; __syncthreads();
    for (int o = 128; o > 0; o >>= 1) {
        if (tid < o) { reds[tid] += reds[tid + o]; redq[tid] += redq[tid + o]; }
        __syncthreads();
    }
    const float mu = reds[0] * (1.0f / DIM);
    const float var = redq[0] * (1.0f / DIM) - mu * mu;
    const float rstd = rsqrtf(var + LN_EPS);

    const float4* g4 = (const float4*)gamma;
    const float4* b4 = (const float4*)beta;
    #pragma unroll
    for (int c = tid; c < DIM / 4; c += 256) {
        float4 v = xr[c], g = g4[c], bb = b4[c], o4;
        o4.x = rnd_tf32((v.x - mu) * rstd * g.x + bb.x);
        o4.y = rnd_tf32((v.y - mu) * rstd * g.y + bb.y);
        o4.z = rnd_tf32((v.z - mu) * rstd * g.z + bb.z);
        o4.w = rnd_tf32((v.w - mu) * rstd * g.w + bb.w);
        out[c] = o4;
    }
}

// ---------------- parallel build of per-(b,tt) query lists ----------------
__global__ __launch_bounds__(256) void build_lists2(const int* __restrict__ locs) {
    const int b = blockIdx.x;
    const int tid = threadIdx.x;
    __shared__ int ssum[256];
    __shared__ int cnt[9];

    const int base = tid * 8;
    int v[8];
    int s = 0;
    #pragma unroll
    for (int j = 0; j < 8; j++) { v[j] = locs[b * T_TXT + base + j]; s += v[j]; }
    ssum[tid] = s;
    if (tid < 9) cnt[tid] = 0;
    __syncthreads();
    for (int off = 1; off < 256; off <<= 1) {
        int t = (tid >= off) ? ssum[tid - off] : 0;
        __syncthreads();
        ssum[tid] += t;
        __syncthreads();
    }
    int run = ssum[tid] - s;
    #pragma unroll
    for (int j = 0; j < 8; j++) {
        run += v[j];
        int p = atomicAdd(&cnt[run], 1);
        g_qlist[b][run][p] = base + j;
    }
    __syncthreads();
    if (tid < 9) g_qcount[b][tid] = cnt[tid];
}

// ---------------- masked chunk attention (tf32-rounded output) ----------------
__global__ __launch_bounds__(256) void attn_kernel() {
    const int blk = blockIdx.x;                 // b*72 + h*9 + tt
    const int b = blk / 72;
    const int h = (blk / 9) % 8;
    const int tt = blk % 9;
    const int cnt = g_qcount[b][tt];
    if (cnt == 0) return;

    const int lane = threadIdx.x & 31;
    const int warp = threadIdx.x >> 5;

    if (tt == 0) {
        for (int qi = warp; qi < cnt; qi += 8) {
            int i = g_qlist[b][0][qi];
            float* dst = g_ao + (size_t)(b * T_TXT + i) * INNER + h * DIM_HEAD;
            dst[lane] = 0.f; dst[lane + 32] = 0.f;
        }
        return;
    }

    __shared__ float ksh[64][65];
    __shared__ float vsh[64][65];
    const int base = b * 512 + (tt - 1) * 64;
    for (int idx = threadIdx.x; idx < 4096; idx += 256) {
        int r = idx >> 6, c = idx & 63;
        const float* kvr = g_kv + (size_t)(base + r) * (2 * INNER);
        ksh[r][c] = kvr[h * DIM_HEAD + c];
        vsh[r][c] = kvr[INNER + h * DIM_HEAD + c];
    }
    __syncthreads();

    const float scale = 0.125f;
    for (int qi = warp; qi < cnt; qi += 8) {
        const int i = g_qlist[b][tt][qi];
        const float* qr = g_q + (size_t)(b * T_TXT + i) * INNER + h * DIM_HEAD;
        const float q0 = qr[lane] * scale;
        const float q1 = qr[lane + 32] * scale;

        float s0 = 0.f, s1 = 0.f;
        #pragma unroll
        for (int d = 0; d < 32; d++) {
            float qd = __shfl_sync(0xffffffffu, q0, d);
            s0 += qd * ksh[lane][d];
            s1 += qd * ksh[lane + 32][d];
        }
        #pragma unroll
        for (int d = 0; d < 32; d++) {
            float qd = __shfl_sync(0xffffffffu, q1, d);
            s0 += qd * ksh[lane][d + 32];
            s1 += qd * ksh[lane + 32][d + 32];
        }
        float m = fmaxf(s0, s1);
        #pragma unroll
        for (int o = 16; o > 0; o >>= 1) m = fmaxf(m, __shfl_xor_sync(0xffffffffu, m, o));
        float p0 = __expf(s0 - m), p1 = __expf(s1 - m);
        float sum = p0 + p1;
        #pragma unroll
        for (int o = 16; o > 0; o >>= 1) sum += __shfl_xor_sync(0xffffffffu, sum, o);
        const float inv = 1.f / sum;
        p0 *= inv; p1 *= inv;

        float o0 = 0.f, o1 = 0.f;
        #pragma unroll
        for (int j = 0; j < 32; j++) {
            float pa = __shfl_sync(0xffffffffu, p0, j);
            float pb = __shfl_sync(0xffffffffu, p1, j);
            o0 += pa * vsh[j][lane]      + pb * vsh[j + 32][lane];
            o1 += pa * vsh[j][lane + 32] + pb * vsh[j + 32][lane + 32];
        }
        float* dst = g_ao + (size_t)(b * T_TXT + i) * INNER + h * DIM_HEAD;
        dst[lane]      = rnd_tf32(o0);
        dst[lane + 32] = rnd_tf32(o1);
    }
}

// ---------------- launch ----------------
extern "C" void kernel_launch(void* const* d_in, const int* in_sizes, int n_in,
                              void* d_out, int out_size) {
    const float* x     = (const float*)d_in[0];
    const float* media = (const float*)d_in[1];
    const int*   locs  = (const int*)d_in[2];
    const float* gamma = (const float*)d_in[3];
    const float* beta  = (const float*)d_in[4];
    const float* Wq    = (const float*)d_in[5];
    const float* Wkv   = (const float*)d_in[6];
    const float* Wout  = (const float*)d_in[7];
    float*       out   = (float*)d_out;

    float *p_xn, *p_q, *p_kv, *p_ao, *p_wq, *p_wkv, *p_wout, *p_media;
    cudaGetSymbolAddress((void**)&p_xn, g_xn);
    cudaGetSymbolAddress((void**)&p_q,  g_q);
    cudaGetSymbolAddress((void**)&p_kv, g_kv);
    cudaGetSymbolAddress((void**)&p_ao, g_ao);
    cudaGetSymbolAddress((void**)&p_wq, g_wq_t);
    cudaGetSymbolAddress((void**)&p_wkv, g_wkv_t);
    cudaGetSymbolAddress((void**)&p_wout, g_wout_t);
    cudaGetSymbolAddress((void**)&p_media, g_media_t);

    cudaFuncSetAttribute(tf32gemm_pipe, cudaFuncAttributeMaxDynamicSharedMemorySize, SMEM_BYTES);

    // 0. pre-round weights + media to tf32 (rna)
    cvt_tf32_kernel<<<(DIM * INNER / 4) / 256, 256>>>(Wq, p_wq, DIM * INNER / 4);
    cvt_tf32_kernel<<<(DIM_VIS * 2 * INNER / 4) / 256, 256>>>(Wkv, p_wkv, DIM_VIS * 2 * INNER / 4);
    cvt_tf32_kernel<<<(INNER * DIM / 4) / 256, 256>>>(Wout, p_wout, INNER * DIM / 4);
    cvt_tf32_kernel<<<(KVROWS * DIM_VIS / 4) / 256, 256>>>(media, p_media, KVROWS * DIM_VIS / 4);

    // 1. LayerNorm (tf32-rounded output)
    ln_kernel<<<ROWS, 256>>>(x, gamma, beta);

    // 2. kv = media_flat @ Wkv   (2048 x 1024 x 1024)
    tf32gemm_pipe<<<dim3((2 * INNER) / 128, KVROWS / 128), 256, SMEM_BYTES>>>(
        p_media, p_wkv, p_kv, KVROWS, 2 * INNER, DIM_VIS);
    // 3. q = xn @ Wq             (8192 x 512 x 2048)
    tf32gemm_pipe<<<dim3(INNER / 128, ROWS / 128), 256, SMEM_BYTES>>>(
        p_xn, p_wq, p_q, ROWS, INNER, DIM);
    // 4. query grouping by text_time
    build_lists2<<<BATCH, 256>>>(locs);

    // 5. masked chunk attention (tf32-rounded output)
    attn_kernel<<<BATCH * HEADS * 9, 256>>>();

    // 6. out = ao @ Wout         (8192 x 2048 x 512)
    tf32gemm_pipe<<<dim3(DIM / 128, ROWS / 128), 256, SMEM_BYTES>>>(
        p_ao, p_wout, out, ROWS, DIM, INNER);
}